// round 11
// baseline (speedup 1.0000x reference)
#include <cuda_runtime.h>
#include <cuda_fp16.h>
#include <math_constants.h>
#include <stdint.h>

// SupCon multi-class loss, symmetric-half fused fp16 HMMA + online softmax.
// z: (8192, 128) fp32, labels: (8192,) int32 -> scalar fp32 loss.
// sim = z z^T / TAU is symmetric: compute only block-pairs (I<=J); each
// 128x128 block is folded row-wise (anchors I) and col-wise (anchors J).

#define TAU_F 0.1f
#define LOG2E_F 1.4426950408889634f
#define LN2_F 0.69314718055994531f
#define SCALE_F (LOG2E_F / TAU_F)

#define BSZ 8192
#define DDIM 128
#define BLK 128
#define NB (BSZ / BLK)            // 64
#define NPAIR (NB * (NB + 1) / 2) // 2080
#define NTHR 256

// SMEM in halves; row stride 136 halves (272B) -> conflict-free ldmatrix.
#define RSTR 136
#define A_OFF 0
#define B_OFF (BLK * RSTR)
#define SMEM_BYTES (2 * BLK * RSTR * 2)   // 69632

__device__ __half  g_zhi[BSZ * DDIM];
__device__ float4  g_part2[NB][BSZ];      // [otherBlock][row] partials, 8MB
__device__ double  g_sum;
__device__ int     g_cnt;

// ---------------- asm helpers ----------------
__device__ __forceinline__ float ex2(float x) {
    float y; asm("ex2.approx.ftz.f32 %0, %1;" : "=f"(y) : "f"(x)); return y;
}
__device__ __forceinline__ void cpa16(uint32_t sa, const void* g) {
    asm volatile("cp.async.cg.shared.global [%0], [%1], 16;" :: "r"(sa), "l"(g));
}
__device__ __forceinline__ void ldsm_x4(uint32_t* r, uint32_t addr) {
    asm volatile("ldmatrix.sync.aligned.m8n8.x4.shared.b16 {%0,%1,%2,%3}, [%4];"
                 : "=r"(r[0]), "=r"(r[1]), "=r"(r[2]), "=r"(r[3]) : "r"(addr));
}
__device__ __forceinline__ void mma16816(float* c, const uint32_t* a,
                                         uint32_t b0, uint32_t b1) {
    asm volatile(
        "mma.sync.aligned.m16n8k16.row.col.f32.f16.f16.f32 "
        "{%0,%1,%2,%3}, {%4,%5,%6,%7}, {%8,%9}, {%0,%1,%2,%3};"
        : "+f"(c[0]), "+f"(c[1]), "+f"(c[2]), "+f"(c[3])
        : "r"(a[0]), "r"(a[1]), "r"(a[2]), "r"(a[3]), "r"(b0), "r"(b1));
}

// ---------------- kernels ----------------
__global__ void supcon_convert_kernel(const float* __restrict__ z) {
    int i = blockIdx.x * blockDim.x + threadIdx.x;   // BSZ*DDIM/2 threads
    if (i == 0) { g_sum = 0.0; g_cnt = 0; }
    float2 f = reinterpret_cast<const float2*>(z)[i];
    reinterpret_cast<__half2*>(g_zhi)[i] = __floats2half2_rn(f.x, f.y);
}

__global__ __launch_bounds__(NTHR, 2)
void supcon_main_kernel(const int* __restrict__ labels) {
    extern __shared__ __half sh[];
    const int tid  = threadIdx.x;
    const int lane = tid & 31;
    const int w    = tid >> 5;
    const int wm   = w & 1;          // 2 warps over M (64 rows each)
    const int wn   = w >> 1;         // 4 warps over N (32 cols each)
    const uint32_t sbase = (uint32_t)__cvta_generic_to_shared(sh);

    // decode linear pair index -> (I, J), I <= J
    int k = blockIdx.x, I = 0;
    while (k >= NB - I) { k -= NB - I; ++I; }
    const int J = I + k;
    const bool diag = (I == J);
    const int rowBase = I * BLK, colBase = J * BLK;

    const uint4* zhi4 = reinterpret_cast<const uint4*>(g_zhi);

    // ---- load A (and B unless diag): 128 rows x 16 uint4 each ----
    #pragma unroll
    for (int it = 0; it < 8; ++it) {
        int idx = tid + it * NTHR; int row = idx >> 4, ch = idx & 15;
        cpa16(sbase + (A_OFF + row * RSTR + ch * 8) * 2,
              zhi4 + (rowBase + row) * 16 + ch);
    }
    if (!diag) {
        #pragma unroll
        for (int it = 0; it < 8; ++it) {
            int idx = tid + it * NTHR; int row = idx >> 4, ch = idx & 15;
            cpa16(sbase + (B_OFF + row * RSTR + ch * 8) * 2,
                  zhi4 + (colBase + row) * 16 + ch);
        }
    }
    asm volatile("cp.async.commit_group;" ::: "memory");
    asm volatile("cp.async.wait_group 0;" ::: "memory");
    __syncthreads();

    // ---- fragment addresses ----
    const int bB = diag ? A_OFF : B_OFF;
    const int arow = lane & 15, akad = (lane >> 4) * 8;
    uint32_t aAddr[4];
    #pragma unroll
    for (int mt = 0; mt < 4; ++mt)
        aAddr[mt] = sbase + (A_OFF + (wm * 64 + mt * 16 + arow) * RSTR + akad) * 2;
    const int brow = ((lane >> 4) << 3) + (lane & 7);
    const int bkad = ((lane >> 3) & 1) * 8;
    uint32_t bAddr[2];
    #pragma unroll
    for (int bt = 0; bt < 2; ++bt)
        bAddr[bt] = sbase + (bB + (wn * 32 + bt * 16 + brow) * RSTR + bkad) * 2;

    // ---- GEMM: 128x128x128, warp tile 64x32, acc 64/thread ----
    float acc[4][4][4];
    #pragma unroll
    for (int mt = 0; mt < 4; ++mt)
        #pragma unroll
        for (int nt = 0; nt < 4; ++nt)
            #pragma unroll
            for (int e = 0; e < 4; ++e) acc[mt][nt][e] = 0.f;

    #pragma unroll
    for (int kc = 0; kc < 8; ++kc) {
        uint32_t ah[4][4], bh[2][4];
        #pragma unroll
        for (int mt = 0; mt < 4; ++mt) ldsm_x4(ah[mt], aAddr[mt] + kc * 32);
        #pragma unroll
        for (int bt = 0; bt < 2; ++bt) ldsm_x4(bh[bt], bAddr[bt] + kc * 32);
        #pragma unroll
        for (int mt = 0; mt < 4; ++mt)
            #pragma unroll
            for (int bt = 0; bt < 2; ++bt) {
                mma16816(acc[mt][bt * 2],     ah[mt], bh[bt][0], bh[bt][1]);
                mma16816(acc[mt][bt * 2 + 1], ah[mt], bh[bt][2], bh[bt][3]);
            }
    }
    __syncthreads();   // all smem reads done -> smem reusable for reductions

    // thread-local row r in [0,8): local row = wm*64 + (r>>1)*16 + ((r&1)<<3) + lane>>2
    // thread-local col j in [0,8): local col = wn*32 + (j>>1)*8 + (lane&3)*2 + (j&1)
    // acc element for (r, j): acc[r>>1][j>>1][((r&1)<<1) | (j&1)]
    int li[8], lc[8];
    #pragma unroll
    for (int r = 0; r < 8; ++r)
        li[r] = __ldg(labels + rowBase + wm * 64 + (r >> 1) * 16 + ((r & 1) << 3) + (lane >> 2));
    #pragma unroll
    for (int j = 0; j < 8; ++j)
        lc[j] = __ldg(labels + colBase + wn * 32 + (j >> 1) * 8 + (lane & 3) * 2 + (j & 1));

    float4* red_row = reinterpret_cast<float4*>(sh);          // [128][4] (8KB)
    float4* red_col = reinterpret_cast<float4*>(sh) + 512;    // [128][2] (4KB)

    // ---- row fold: 2 passes of 4 rows ----
    #pragma unroll
    for (int p = 0; p < 2; ++p) {
        float rm[4], rs[4], rps[4]; int rpc[4];
        #pragma unroll
        for (int rr = 0; rr < 4; ++rr) {
            const int r = p * 4 + rr;
            const int growr = rowBase + wm * 64 + (r >> 1) * 16 + ((r & 1) << 3) + (lane >> 2);
            float lh[8], tmax = -CUDART_INF_F, tps = 0.f; int tpc = 0;
            #pragma unroll
            for (int j = 0; j < 8; ++j) {
                float v = acc[r >> 1][j >> 1][((r & 1) << 1) | (j & 1)];
                int gcol = colBase + wn * 32 + (j >> 1) * 8 + (lane & 3) * 2 + (j & 1);
                bool dg = (gcol == growr);                  // only in diag blocks
                if (!dg && lc[j] == li[r]) { tps += v; tpc += 1; }
                float l = dg ? -CUDART_INF_F : v * SCALE_F;
                lh[j] = l;
                tmax = fmaxf(tmax, l);
            }
            float ss = 0.f;
            #pragma unroll
            for (int j = 0; j < 8; ++j) ss += ex2(lh[j] - tmax);
            rm[rr] = tmax; rs[rr] = ss; rps[rr] = tps; rpc[rr] = tpc;
        }
        // merge across the 4 threads (lane&3) sharing each row
        #pragma unroll
        for (int rr = 0; rr < 4; ++rr) {
            #pragma unroll
            for (int ox = 1; ox <= 2; ox <<= 1) {
                float mo  = __shfl_xor_sync(0xFFFFFFFFu, rm[rr],  ox);
                float so  = __shfl_xor_sync(0xFFFFFFFFu, rs[rr],  ox);
                float pso = __shfl_xor_sync(0xFFFFFFFFu, rps[rr], ox);
                int   pco = __shfl_xor_sync(0xFFFFFFFFu, rpc[rr], ox);
                float nm = fmaxf(rm[rr], mo);
                rs[rr] = rs[rr] * ex2(rm[rr] - nm) + so * ex2(mo - nm);
                rm[rr] = nm; rps[rr] += pso; rpc[rr] += pco;
            }
        }
        if ((lane & 3) == 0) {
            #pragma unroll
            for (int rr = 0; rr < 4; ++rr) {
                const int r = p * 4 + rr;
                const int lrow = wm * 64 + (r >> 1) * 16 + ((r & 1) << 3) + (lane >> 2);
                red_row[lrow * 4 + wn] =
                    make_float4(rm[rr], rs[rr], rps[rr], __int_as_float(rpc[rr]));
            }
        }
    }

    // ---- col fold (symmetric contribution), skip for diagonal blocks ----
    if (!diag) {
        #pragma unroll
        for (int p = 0; p < 2; ++p) {
            float cm[4], cs[4], cps[4]; int cpc[4];
            #pragma unroll
            for (int jj = 0; jj < 4; ++jj) {
                const int j = p * 4 + jj;
                float lh[8], tmax = -CUDART_INF_F, tps = 0.f; int tpc = 0;
                #pragma unroll
                for (int r = 0; r < 8; ++r) {
                    float v = acc[r >> 1][j >> 1][((r & 1) << 1) | (j & 1)];
                    if (lc[j] == li[r]) { tps += v; tpc += 1; }   // no diag here
                    float l = v * SCALE_F;
                    lh[r] = l;
                    tmax = fmaxf(tmax, l);
                }
                float ss = 0.f;
                #pragma unroll
                for (int r = 0; r < 8; ++r) ss += ex2(lh[r] - tmax);
                cm[jj] = tmax; cs[jj] = ss; cps[jj] = tps; cpc[jj] = tpc;
            }
            // merge across the 8 threads (lane>>2) sharing each col
            #pragma unroll
            for (int jj = 0; jj < 4; ++jj) {
                #pragma unroll
                for (int ox = 4; ox <= 16; ox <<= 1) {
                    float mo  = __shfl_xor_sync(0xFFFFFFFFu, cm[jj],  ox);
                    float so  = __shfl_xor_sync(0xFFFFFFFFu, cs[jj],  ox);
                    float pso = __shfl_xor_sync(0xFFFFFFFFu, cps[jj], ox);
                    int   pco = __shfl_xor_sync(0xFFFFFFFFu, cpc[jj], ox);
                    float nm = fmaxf(cm[jj], mo);
                    cs[jj] = cs[jj] * ex2(cm[jj] - nm) + so * ex2(mo - nm);
                    cm[jj] = nm; cps[jj] += pso; cpc[jj] += pco;
                }
            }
            if (lane < 4) {
                #pragma unroll
                for (int jj = 0; jj < 4; ++jj) {
                    const int j = p * 4 + jj;
                    const int lcol = wn * 32 + (j >> 1) * 8 + (lane & 3) * 2 + (j & 1);
                    red_col[lcol * 2 + wm] =
                        make_float4(cm[jj], cs[jj], cps[jj], __int_as_float(cpc[jj]));
                }
            }
        }
    }
    __syncthreads();

    // ---- final per-row partial writes to gmem ----
    if (tid < BLK) {
        float4 p0 = red_row[tid * 4 + 0], p1 = red_row[tid * 4 + 1];
        float4 p2 = red_row[tid * 4 + 2], p3 = red_row[tid * 4 + 3];
        float M = fmaxf(fmaxf(p0.x, p1.x), fmaxf(p2.x, p3.x));
        float S = p0.y * ex2(p0.x - M) + p1.y * ex2(p1.x - M) +
                  p2.y * ex2(p2.x - M) + p3.y * ex2(p3.x - M);
        float PS = p0.z + p1.z + p2.z + p3.z;
        int PC = __float_as_int(p0.w) + __float_as_int(p1.w) +
                 __float_as_int(p2.w) + __float_as_int(p3.w);
        g_part2[J][rowBase + tid] = make_float4(M, S, PS, __int_as_float(PC));
    } else if (!diag) {
        const int c = tid - BLK;
        float4 p0 = red_col[c * 2 + 0], p1 = red_col[c * 2 + 1];
        float M = fmaxf(p0.x, p1.x);
        float S = p0.y * ex2(p0.x - M) + p1.y * ex2(p1.x - M);
        float PS = p0.z + p1.z;
        int PC = __float_as_int(p0.w) + __float_as_int(p1.w);
        g_part2[I][colBase + c] = make_float4(M, S, PS, __int_as_float(PC));
    }
}

__global__ void supcon_merge_kernel() {
    int i = blockIdx.x * blockDim.x + threadIdx.x;   // BSZ threads
    float M = -CUDART_INF_F, S = 0.f, PS = 0.f; int PC = 0;
    #pragma unroll 4
    for (int p = 0; p < NB; ++p) {
        float4 v = g_part2[p][i];
        float nm = fmaxf(M, v.x);
        S = S * ex2(M - nm) + v.y * ex2(v.x - nm);
        M = nm; PS += v.z; PC += __float_as_int(v.w);
    }
    double loss = 0.0; int valid = 0;
    if (PC > 0) {
        float lse = LN2_F * (M + log2f(S));   // natural-log lse
        loss = (double)(lse - PS / (TAU_F * (float)PC));
        valid = 1;
    }
    #pragma unroll
    for (int o = 16; o; o >>= 1) {
        loss  += __shfl_down_sync(0xFFFFFFFFu, loss, o);
        valid += __shfl_down_sync(0xFFFFFFFFu, valid, o);
    }
    if ((threadIdx.x & 31) == 0) {
        atomicAdd(&g_sum, loss);
        atomicAdd(&g_cnt, valid);
    }
}

__global__ void supcon_final_kernel(float* __restrict__ out) {
    int c = g_cnt; if (c < 1) c = 1;
    out[0] = (float)(g_sum / (double)c);
}

extern "C" void kernel_launch(void* const* d_in, const int* in_sizes, int n_in,
                              void* d_out, int out_size) {
    const float* z      = (const float*)d_in[0];
    const int*   labels = (const int*)d_in[1];
    float*       out    = (float*)d_out;

    static bool attr_set = false;
    if (!attr_set) {
        cudaFuncSetAttribute(supcon_main_kernel,
                             cudaFuncAttributeMaxDynamicSharedMemorySize,
                             SMEM_BYTES);
        attr_set = true;
    }

    supcon_convert_kernel<<<(BSZ * DDIM / 2) / 256, 256>>>(z);
    supcon_main_kernel<<<NPAIR, NTHR, SMEM_BYTES>>>(labels);
    supcon_merge_kernel<<<BSZ / 256, 256>>>();
    supcon_final_kernel<<<1, 1>>>(out);
}